// round 6
// baseline (speedup 1.0000x reference)
#include <cuda_runtime.h>
#include <cuda_bf16.h>
#include <cstdint>

#define TV 16384
#define V_SZ 1024
#define T_SZ 16
#define B_SZ 256
#define JT 8              // W rows per CTA
#define THREADS 256       // one thread per batch element
#define QF 4096           // floats per quarter-row (4 t-slots)
#define QBYTES (QF * 4)   // 16 KB
#define NBUF 3            // triple buffer
#define NQ (JT * 4)       // quarters per CTA

__device__ __forceinline__ void mbar_wait(uint32_t mbar, int parity) {
    asm volatile(
        "{\n\t"
        ".reg .pred P;\n\t"
        "WL_%=:\n\t"
        "mbarrier.try_wait.parity.acquire.cta.shared::cta.b64 P, [%0], %1, 0x989680;\n\t"
        "@P bra.uni WD_%=;\n\t"
        "bra.uni WL_%=;\n\t"
        "WD_%=:\n\t"
        "}" :: "r"(mbar), "r"(parity) : "memory");
}

// ---------------------------------------------------------------------------
// Per CTA: JT=8 consecutive W rows x all 256 batches.
// Each row is streamed densely as 4 x 16KB quarters via cp.async.bulk
// (single-thread issue, mbarrier complete_tx), triple-buffered so 2 quarters
// are always in flight. Threads gather their 4 t-slot elements per quarter
// from smem; per-row sums accumulate in registers; one 32B store per thread
// per CTA block of rows.
// ---------------------------------------------------------------------------
__global__ void __launch_bounds__(THREADS, 4) gather_sum_relu_kernel(
    const void* __restrict__ x_raw,     // [B, T] int64 or int32
    const float* __restrict__ W,        // [TV, TV] row-major
    const float* __restrict__ bias,     // [TV]
    float* __restrict__ out)            // [B, TV]
{
    extern __shared__ float buf[];                       // NBUF * QF floats
    __shared__ __align__(8) unsigned long long mbar[NBUF];

    const int tid = threadIdx.x;                         // = batch b
    const int j0 = blockIdx.x * JT;

    const uint32_t buf_sa  = (uint32_t)__cvta_generic_to_shared(buf);
    const uint32_t mbar_sa = (uint32_t)__cvta_generic_to_shared(mbar);

    if (tid == 0) {
        #pragma unroll
        for (int i = 0; i < NBUF; i++)
            asm volatile("mbarrier.init.shared.b64 [%0], 1;"
                         :: "r"(mbar_sa + i * 8) : "memory");
    }

    // ---- gather indices (dtype-robust: int64 values in [0,V) look like (v,0)) ----
    const long long* x64 = (const long long*)x_raw;
    const int*       x32 = (const int*)x_raw;
    long long v64[T_SZ];
    bool ok64 = true;
    #pragma unroll
    for (int t = 0; t < T_SZ; t++) {
        v64[t] = x64[tid * T_SZ + t];
        if (v64[t] < 0 || v64[t] >= V_SZ) ok64 = false;
    }
    int c[T_SZ];   // offset within the quarter that owns t-slot t
    #pragma unroll
    for (int t = 0; t < T_SZ; t++) {
        int xi = ok64 ? (int)v64[t] : x32[tid * T_SZ + t];
        c[t] = xi + (t & 3) * V_SZ;          // t-slot t lives in quarter t>>2
    }
    __syncthreads();                         // mbar init visible

    // Issue quarter q (row q>>2, quarter-in-row q&3) into buffer q%NBUF.
    auto issue = [&](int q) {
        const int bi = q % NBUF;
        const float* src = W + (size_t)(j0 + (q >> 2)) * TV + (q & 3) * QF;
        const uint32_t mb = mbar_sa + bi * 8;
        const uint32_t dst = buf_sa + bi * QBYTES;
        asm volatile("mbarrier.arrive.expect_tx.shared.b64 _, [%0], %1;"
                     :: "r"(mb), "r"(QBYTES) : "memory");
        asm volatile("cp.async.bulk.shared::cta.global.mbarrier::complete_tx::bytes "
                     "[%0], [%1], %2, [%3];"
                     :: "r"(dst), "l"(src), "r"(QBYTES), "r"(mb) : "memory");
    };

    if (tid == 0) { issue(0); issue(1); issue(2); }

    int ph[NBUF] = {0, 0, 0};
    float acc[JT];

    for (int k = 0; k < NQ; k++) {
        const int bi = k % NBUF;
        mbar_wait(mbar_sa + bi * 8, ph[bi]);
        ph[bi] ^= 1;

        const float* b = buf + bi * QF;
        const int q = k & 3;                 // quarter-in-row -> t-slots 4q..4q+3
        float s;
        if      (q == 0) s = b[c[0]]  + b[c[1]]  + b[c[2]]  + b[c[3]];
        else if (q == 1) s = b[c[4]]  + b[c[5]]  + b[c[6]]  + b[c[7]];
        else if (q == 2) s = b[c[8]]  + b[c[9]]  + b[c[10]] + b[c[11]];
        else             s = b[c[12]] + b[c[13]] + b[c[14]] + b[c[15]];

        const int row = k >> 2;
        acc[row] = (q == 0) ? s : (acc[row] + s);

        __syncthreads();                     // all threads done reading buf[bi]
        if (tid == 0 && k + NBUF < NQ) issue(k + NBUF);
    }

    // ---- bias + relu + 32B contiguous store per thread (one DRAM sector) ----
    float r[JT];
    #pragma unroll
    for (int jj = 0; jj < JT; jj++) {
        float v = acc[jj] + bias[j0 + jj];
        r[jj] = v > 0.f ? v : 0.f;
    }
    float4* o = (float4*)(out + (size_t)tid * TV + j0);
    o[0] = make_float4(r[0], r[1], r[2], r[3]);
    o[1] = make_float4(r[4], r[5], r[6], r[7]);
}

extern "C" void kernel_launch(void* const* d_in, const int* in_sizes, int n_in,
                              void* d_out, int out_size) {
    const void*  x    = d_in[0];                 // [256, 16] int64/int32
    const float* W    = (const float*)d_in[1];   // [16384, 16384]
    const float* bias = (const float*)d_in[2];   // [16384]
    float* out = (float*)d_out;                  // [256, 16384]

    const int smem_bytes = NBUF * QBYTES;        // 48 KB -> 4 CTAs/SM
    static bool attr_set = false;
    if (!attr_set) {
        cudaFuncSetAttribute(gather_sum_relu_kernel,
                             cudaFuncAttributeMaxDynamicSharedMemorySize, smem_bytes);
        attr_set = true;
    }

    gather_sum_relu_kernel<<<TV / JT, THREADS, smem_bytes>>>(x, W, bias, out);
}